// round 14
// baseline (speedup 1.0000x reference)
#include <cuda_runtime.h>
#include <cuda_fp16.h>
#include <math.h>
#include <stdint.h>

#define OBSD 194
#define HD   64
#define AD   5
#define ED   3
#define BLOCK 128
#define ROWS  64
#define NCH1  7
#define G1H   (NCH1 * 2048)          // GEMM1 B image, uint32 units
#define GTOT32 (G1H + 2 * 2048)      // + W2, Wc2 images

__device__ __align__(16) uint32_t g_b[GTOT32];

__device__ __forceinline__ uint32_t smem_u32(const void* p) {
    uint32_t a;
    asm("{ .reg .u64 t; cvta.to.shared.u64 t, %1; cvt.u32.u64 %0, t; }" : "=r"(a) : "l"(p));
    return a;
}
__device__ __forceinline__ float tanha(float x) {
    float y; asm("tanh.approx.f32 %0, %1;" : "=f"(y) : "f"(x)); return y;
}
__device__ __forceinline__ void mma16(float* c, uint32_t a0, uint32_t a1, uint32_t a2,
                                      uint32_t a3, uint32_t b0, uint32_t b1) {
    asm volatile("mma.sync.aligned.m16n8k16.row.col.f32.f16.f16.f32 "
                 "{%0,%1,%2,%3},{%4,%5,%6,%7},{%8,%9},{%0,%1,%2,%3};"
                 : "+f"(c[0]), "+f"(c[1]), "+f"(c[2]), "+f"(c[3])
                 : "r"(a0), "r"(a1), "r"(a2), "r"(a3), "r"(b0), "r"(b1));
}
__device__ __forceinline__ void ldsm4(uint32_t* r, uint32_t addr) {
    asm volatile("ldmatrix.sync.aligned.m8n8.x4.shared.b16 {%0,%1,%2,%3}, [%4];"
                 : "=r"(r[0]), "=r"(r[1]), "=r"(r[2]), "=r"(r[3]) : "r"(addr));
}
__device__ __forceinline__ uint32_t pack_h2(float lo, float hi) {
    half2 h = __floats2half2_rn(lo, hi);
    return *reinterpret_cast<uint32_t*>(&h);
}

// ---------- prep: bake fp16 B fragment images (unchanged) ----------
__global__ void prep_b(const float* __restrict__ W1, const float* __restrict__ Wc1,
                       const float* __restrict__ W2, const float* __restrict__ Wc2) {
    int idx = blockIdx.x * blockDim.x + threadIdx.x;
    if (idx >= GTOT32) return;
    int lane = (idx >> 2) & 31;
    int q    = idx & 3;
    int g = lane >> 2, tg = lane & 3;
    int r = q & 1;
    float lo = 0.f, hi = 0.f;
    if (idx < G1H) {
        int c     = idx >> 11;
        int f     = (idx >> 10) & 1;
        int np    = (idx >> 7) & 7;
        int ntAll = np * 2 + (q >> 1);
        int k0 = 32 * c + 16 * f + 2 * tg + 8 * r;
        int n  = 8 * ntAll + g;
        if (k0 < OBSD)     lo = (n < HD) ? W1[k0 * HD + n]       : Wc1[k0 * HD + n - HD];
        if (k0 + 1 < OBSD) hi = (n < HD) ? W1[(k0 + 1) * HD + n] : Wc1[(k0 + 1) * HD + n - HD];
    } else {
        int t   = idx - G1H;
        int mat = t >> 11;
        int kf  = (t >> 9) & 3;
        int np  = (t >> 7) & 3;
        int ntAll = np * 2 + (q >> 1);
        int k0 = 16 * kf + 2 * tg + 8 * r;
        int n  = 8 * ntAll + g;
        const float* Wm = mat ? Wc2 : W2;
        lo = Wm[k0 * HD + n];
        hi = Wm[(k0 + 1) * HD + n];
    }
    half2 h = __floats2half2_rn(lo, hi);
    g_b[idx] = *reinterpret_cast<uint32_t*>(&h);
}

// ---------- main: 128 threads, 64 samples/CTA, 4 CTAs/SM ----------
// GEMM1: A fragments loaded DIRECTLY from x (no smem, no barriers, full unroll)
__global__ void __launch_bounds__(BLOCK, 4)
agent_mma(const float* __restrict__ x,   const int* __restrict__ action,
          const float* __restrict__ b1,  const float* __restrict__ b2,
          const float* __restrict__ Wh,  const float* __restrict__ bh,
          const float* __restrict__ bc1, const float* __restrict__ bc2,
          const float* __restrict__ Wc3, const float* __restrict__ bc3,
          float* __restrict__ out, int Bn)
{
    __shared__ __align__(16) float spool[4160];   // GEMM2 staging (2x4KB) + fbuf (64x65)
    __shared__ float whs[ED * HD * AD];
    __shared__ float bhs[16];
    __shared__ float b1s[HD], b2s[HD], bc1s[HD], bc2s[HD], wc3s[HD];
    __shared__ float valbuf[2][ROWS];

    uint32_t* sp32 = (uint32_t*)spool;
    const uint4* gb4 = (const uint4*)g_b;
    const int   G2   = G1H / 4;
    const uint32_t sbase = smem_u32(spool);

    const int tid   = threadIdx.x;
    const int lane  = tid & 31;
    const int warp  = tid >> 5;
    const int warpM = warp & 1;
    const int warpN = warp >> 1;
    const int g     = lane >> 2;
    const int tg    = lane & 3;
    const int rb2   = warpM * 32;
    const int s0    = blockIdx.x * ROWS;

    for (int i = tid; i < ED * HD * AD; i += BLOCK) whs[i] = Wh[i];
    if (tid < ED * AD) bhs[tid] = bh[tid];
    if (tid < HD) {
        b1s[tid] = b1[tid];   b2s[tid] = b2[tid];
        bc1s[tid] = bc1[tid]; bc2s[tid] = bc2[tid]; wc3s[tid] = Wc3[tid];
    }
    const float bc3v = __ldg(&bc3[0]);

    // per-lane clamped x row pointers: [t][half] -> row rb2 + 16t + g + 8*half
    const float* rp[2][2];
    #pragma unroll
    for (int t = 0; t < 2; t++)
        #pragma unroll
        for (int h = 0; h < 2; h++) {
            int row = s0 + rb2 + 16 * t + g + 8 * h;
            if (row >= Bn) row = Bn - 1;
            rp[t][h] = x + (size_t)row * OBSD;
        }

    float acc[2][8][4];
    #pragma unroll
    for (int t = 0; t < 2; t++)
        #pragma unroll
        for (int nt = 0; nt < 8; nt++)
            #pragma unroll
            for (int i = 0; i < 4; i++) acc[t][nt][i] = 0.f;

    // ================= GEMM1: C[64x128] = X @ [W1|Wc1] — barrier-free =================
    const uint4* gbc = gb4 + warpN * 128 + lane;
    #pragma unroll
    for (int c = 0; c < NCH1; c++) {
        #pragma unroll
        for (int f = 0; f < 2; f++) {
            // B fragments (L2-hot fragment image)
            uint4 bq0 = __ldg(gbc + c * 512 + f * 256);
            uint4 bq1 = __ldg(gbc + c * 512 + f * 256 + 32);
            uint4 bq2 = __ldg(gbc + c * 512 + f * 256 + 64);
            uint4 bq3 = __ldg(gbc + c * 512 + f * 256 + 96);

            #pragma unroll
            for (int t = 0; t < 2; t++) {
                const int col = 32 * c + 16 * f + 2 * tg;
                float2 v0, v1, v2, v3;
                if (32 * c + 16 * f <= 178) {        // compile-time: chunks 0..5 (+ c6 none)
                    v0 = *(const float2*)(rp[t][0] + col);
                    v1 = *(const float2*)(rp[t][1] + col);
                    v2 = *(const float2*)(rp[t][0] + col + 8);
                    v3 = *(const float2*)(rp[t][1] + col + 8);
                } else {                              // tail chunk: per-pair predicates
                    const float2 z = make_float2(0.f, 0.f);
                    bool p0 = (col + 1) < OBSD;
                    bool p2 = (col + 9) < OBSD;
                    v0 = p0 ? *(const float2*)(rp[t][0] + col) : z;
                    v1 = p0 ? *(const float2*)(rp[t][1] + col) : z;
                    v2 = p2 ? *(const float2*)(rp[t][0] + col + 8) : z;
                    v3 = p2 ? *(const float2*)(rp[t][1] + col + 8) : z;
                }
                uint32_t A0 = pack_h2(v0.x, v0.y);
                uint32_t A1 = pack_h2(v1.x, v1.y);
                uint32_t A2 = pack_h2(v2.x, v2.y);
                uint32_t A3 = pack_h2(v3.x, v3.y);

                mma16(acc[t][0], A0, A1, A2, A3, bq0.x, bq0.y);
                mma16(acc[t][1], A0, A1, A2, A3, bq0.z, bq0.w);
                mma16(acc[t][2], A0, A1, A2, A3, bq1.x, bq1.y);
                mma16(acc[t][3], A0, A1, A2, A3, bq1.z, bq1.w);
                mma16(acc[t][4], A0, A1, A2, A3, bq2.x, bq2.y);
                mma16(acc[t][5], A0, A1, A2, A3, bq2.z, bq2.w);
                mma16(acc[t][6], A0, A1, A2, A3, bq3.x, bq3.y);
                mma16(acc[t][7], A0, A1, A2, A3, bq3.z, bq3.w);
            }
        }
    }

    // epilogue1: bias + tanh (warpN0 = actor H, warpN1 = critic H)
    {
        const float* bA = warpN ? bc1s : b1s;
        #pragma unroll
        for (int t = 0; t < 2; t++)
            #pragma unroll
            for (int nt = 0; nt < 8; nt++) {
                int n0 = 8 * nt + 2 * tg;
                acc[t][nt][0] = tanha(acc[t][nt][0] + bA[n0]);
                acc[t][nt][1] = tanha(acc[t][nt][1] + bA[n0 + 1]);
                acc[t][nt][2] = tanha(acc[t][nt][2] + bA[n0]);
                acc[t][nt][3] = tanha(acc[t][nt][3] + bA[n0 + 1]);
            }
    }

    // ================= GEMM2: critic pass (mat=1) then actor pass (mat=0) =================
    #pragma unroll 1
    for (int pp = 0; pp < 2; pp++) {
        const int mat = (pp == 0) ? 1 : 0;
        float acc2[2][4][4];
        #pragma unroll
        for (int t = 0; t < 2; t++)
            #pragma unroll
            for (int nt = 0; nt < 4; nt++)
                #pragma unroll
                for (int i = 0; i < 4; i++) acc2[t][nt][i] = 0.f;

        __syncthreads();
        if (warpN == mat) {                 // owner warps stage H (both kh buffers)
            #pragma unroll
            for (int t = 0; t < 2; t++)
                #pragma unroll
                for (int nt = 0; nt < 8; nt++) {
                    int kh = nt >> 2, kg = nt & 3;
                    uint32_t* buf = sp32 + kh * 1024;
                    int perm = (g + 2 * kg) & 7;
                    int rga = 4 * warpM + 2 * t;
                    buf[(rga * 4 + kg) * 32 + perm * 4 + tg] =
                        pack_h2(acc[t][nt][0], acc[t][nt][1]);
                    buf[((rga + 1) * 4 + kg) * 32 + perm * 4 + tg] =
                        pack_h2(acc[t][nt][2], acc[t][nt][3]);
                }
        }
        __syncthreads();

        #pragma unroll
        for (int kh = 0; kh < 2; kh++) {
            const uint32_t abuf = sbase + kh * 4096;
            #pragma unroll
            for (int f = 0; f < 2; f++) {
                uint32_t A[2][4];
                #pragma unroll
                for (int t = 0; t < 2; t++) {
                    int mi = lane >> 3;
                    int rg = 4 * warpM + 2 * t + (mi & 1);
                    int kg = 2 * f + (mi >> 1);
                    int rowp = ((lane & 7) + 2 * kg) & 7;
                    ldsm4(A[t], abuf + (rg * 4 + kg) * 128 + rowp * 16);
                }
                int kf = kh * 2 + f;
                #pragma unroll
                for (int npi = 0; npi < 2; npi++) {
                    uint4 bq = __ldg(&gb4[G2 + mat * 512 + kf * 128
                                          + warpN * 64 + npi * 32 + lane]);
                    mma16(acc2[0][2*npi],   A[0][0], A[0][1], A[0][2], A[0][3], bq.x, bq.y);
                    mma16(acc2[1][2*npi],   A[1][0], A[1][1], A[1][2], A[1][3], bq.x, bq.y);
                    mma16(acc2[0][2*npi+1], A[0][0], A[0][1], A[0][2], A[0][3], bq.z, bq.w);
                    mma16(acc2[1][2*npi+1], A[1][0], A[1][1], A[1][2], A[1][3], bq.z, bq.w);
                }
            }
        }

        if (mat == 1) {
            float vr[4] = {0.f, 0.f, 0.f, 0.f};
            #pragma unroll
            for (int t = 0; t < 2; t++)
                #pragma unroll
                for (int nt = 0; nt < 4; nt++) {
                    int n0 = warpN * 32 + 8 * nt + 2 * tg;
                    vr[2*t]   = fmaf(tanha(acc2[t][nt][0] + bc2s[n0]),     wc3s[n0],     vr[2*t]);
                    vr[2*t]   = fmaf(tanha(acc2[t][nt][1] + bc2s[n0 + 1]), wc3s[n0 + 1], vr[2*t]);
                    vr[2*t+1] = fmaf(tanha(acc2[t][nt][2] + bc2s[n0]),     wc3s[n0],     vr[2*t+1]);
                    vr[2*t+1] = fmaf(tanha(acc2[t][nt][3] + bc2s[n0 + 1]), wc3s[n0 + 1], vr[2*t+1]);
                }
            #pragma unroll
            for (int i = 0; i < 4; i++) {
                vr[i] += __shfl_xor_sync(0xFFFFFFFF, vr[i], 1);
                vr[i] += __shfl_xor_sync(0xFFFFFFFF, vr[i], 2);
            }
            if (tg == 0) {
                valbuf[warpN][rb2 + g]      = vr[0];
                valbuf[warpN][rb2 + g + 8]  = vr[1];
                valbuf[warpN][rb2 + g + 16] = vr[2];
                valbuf[warpN][rb2 + g + 24] = vr[3];
            }
        } else {
            __syncthreads();
            float* fbuf = spool;     // 64 x 65 fp32
            #pragma unroll
            for (int t = 0; t < 2; t++)
                #pragma unroll
                for (int nt = 0; nt < 4; nt++) {
                    int n0 = warpN * 32 + 8 * nt + 2 * tg;
                    int r0 = (rb2 + 16 * t + g) * 65;
                    int r1 = (rb2 + 16 * t + g + 8) * 65;
                    fbuf[r0 + n0]     = tanha(acc2[t][nt][0] + b2s[n0]);
                    fbuf[r0 + n0 + 1] = tanha(acc2[t][nt][1] + b2s[n0 + 1]);
                    fbuf[r1 + n0]     = tanha(acc2[t][nt][2] + b2s[n0]);
                    fbuf[r1 + n0 + 1] = tanha(acc2[t][nt][3] + b2s[n0 + 1]);
                }
            __syncthreads();
        }
    }

    // ================= per-sample head =================
    if (tid < ROWS) {
        const float* fbuf = spool;
        int s = s0 + tid;
        int sr = (s < Bn) ? s : (Bn - 1);
        const float* xrow = x + (size_t)sr * OBSD;
        float x0 = __ldg(&xrow[0]), x1v = __ldg(&xrow[1]), x2v = __ldg(&xrow[2]);
        int ev = 0; float bx = x0;
        if (x1v > bx) { bx = x1v; ev = 1; }
        if (x2v > bx) { ev = 2; }

        float lg[AD];
        #pragma unroll
        for (int a = 0; a < AD; a++) lg[a] = bhs[ev * AD + a];
        const float* fr  = &fbuf[tid * 65];
        const float* whe = &whs[ev * HD * AD];
        #pragma unroll 8
        for (int k = 0; k < HD; k++) {
            float fk = fr[k];
            #pragma unroll
            for (int a = 0; a < AD; a++) lg[a] = fmaf(fk, whe[k * AD + a], lg[a]);
        }
        float m = lg[0];
        #pragma unroll
        for (int a = 1; a < AD; a++) m = fmaxf(m, lg[a]);
        float se = 0.f;
        #pragma unroll
        for (int a = 0; a < AD; a++) se += __expf(lg[a] - m);
        float lse = __logf(se);
        float ent = 0.f;
        #pragma unroll
        for (int a = 0; a < AD; a++) {
            float lp = lg[a] - m - lse;
            ent -= __expf(lp) * lp;
        }
        int   act  = __ldg(&action[sr]);
        float logp = lg[act] - m - lse;

        if (s < Bn) {
            out[s]          = (float)act;
            out[Bn + s]     = logp;
            out[2 * Bn + s] = ent;
            out[3 * Bn + s] = valbuf[0][tid] + valbuf[1][tid] + bc3v;
        }
    }
}

extern "C" void kernel_launch(void* const* d_in, const int* in_sizes, int n_in,
                              void* d_out, int out_size) {
    const float* x    = (const float*)d_in[0];
    const int*   act  = (const int*)  d_in[1];
    const float* W1   = (const float*)d_in[2];
    const float* b1   = (const float*)d_in[3];
    const float* W2   = (const float*)d_in[4];
    const float* b2   = (const float*)d_in[5];
    const float* Wh   = (const float*)d_in[6];
    const float* bh   = (const float*)d_in[7];
    const float* Wc1  = (const float*)d_in[8];
    const float* bc1  = (const float*)d_in[9];
    const float* Wc2  = (const float*)d_in[10];
    const float* bc2  = (const float*)d_in[11];
    const float* Wc3  = (const float*)d_in[12];
    const float* bc3  = (const float*)d_in[13];
    float* out = (float*)d_out;

    const int Bn = in_sizes[1];

    prep_b<<<(GTOT32 + 255) / 256, 256>>>(W1, Wc1, W2, Wc2);

    const int grid = (Bn + ROWS - 1) / ROWS;
    agent_mma<<<grid, BLOCK>>>(x, act, b1, b2, Wh, bh, bc1, bc2, Wc3, bc3, out, Bn);
}

// round 15
// speedup vs baseline: 1.4574x; 1.4574x over previous
#include <cuda_runtime.h>
#include <cuda_fp16.h>
#include <math.h>
#include <stdint.h>

#define OBSD 194
#define HD   64
#define AD   5
#define ED   3
#define BLOCK 128
#define ROWS  64
#define NCH1  7
#define G1H   (NCH1 * 2048)               // GEMM1 B image, uint32 units
#define GTOT32 (G1H + 2 * 2048 + 512)     // + W2, Wc2 images + head image

__device__ __align__(16) uint32_t g_b[GTOT32];

__device__ __forceinline__ uint32_t smem_u32(const void* p) {
    uint32_t a;
    asm("{ .reg .u64 t; cvta.to.shared.u64 t, %1; cvt.u32.u64 %0, t; }" : "=r"(a) : "l"(p));
    return a;
}
__device__ __forceinline__ float tanha(float x) {
    float y; asm("tanh.approx.f32 %0, %1;" : "=f"(y) : "f"(x)); return y;
}
__device__ __forceinline__ void mma16(float* c, uint32_t a0, uint32_t a1, uint32_t a2,
                                      uint32_t a3, uint32_t b0, uint32_t b1) {
    asm volatile("mma.sync.aligned.m16n8k16.row.col.f32.f16.f16.f32 "
                 "{%0,%1,%2,%3},{%4,%5,%6,%7},{%8,%9},{%0,%1,%2,%3};"
                 : "+f"(c[0]), "+f"(c[1]), "+f"(c[2]), "+f"(c[3])
                 : "r"(a0), "r"(a1), "r"(a2), "r"(a3), "r"(b0), "r"(b1));
}
__device__ __forceinline__ void ldsm4(uint32_t* r, uint32_t addr) {
    asm volatile("ldmatrix.sync.aligned.m8n8.x4.shared.b16 {%0,%1,%2,%3}, [%4];"
                 : "=r"(r[0]), "=r"(r[1]), "=r"(r[2]), "=r"(r[3]) : "r"(addr));
}
__device__ __forceinline__ uint32_t pack_h2(float lo, float hi) {
    half2 h = __floats2half2_rn(lo, hi);
    return *reinterpret_cast<uint32_t*>(&h);
}

// ---------- prep: bake fp16 B fragment images (+ head image) ----------
__global__ void prep_b(const float* __restrict__ W1, const float* __restrict__ Wc1,
                       const float* __restrict__ W2, const float* __restrict__ Wc2,
                       const float* __restrict__ Wh) {
    int idx = blockIdx.x * blockDim.x + threadIdx.x;
    if (idx >= GTOT32) return;
    int lane = (idx >> 2) & 31;
    int q    = idx & 3;
    int g = lane >> 2, tg = lane & 3;
    int r = q & 1;
    float lo = 0.f, hi = 0.f;
    if (idx < G1H) {
        int c     = idx >> 11;
        int f     = (idx >> 10) & 1;
        int np    = (idx >> 7) & 7;
        int ntAll = np * 2 + (q >> 1);
        int k0 = 32 * c + 16 * f + 2 * tg + 8 * r;
        int n  = 8 * ntAll + g;
        if (k0 < OBSD)     lo = (n < HD) ? W1[k0 * HD + n]       : Wc1[k0 * HD + n - HD];
        if (k0 + 1 < OBSD) hi = (n < HD) ? W1[(k0 + 1) * HD + n] : Wc1[(k0 + 1) * HD + n - HD];
    } else if (idx < G1H + 4096) {
        int t   = idx - G1H;
        int mat = t >> 11;
        int kf  = (t >> 9) & 3;
        int np  = (t >> 7) & 3;
        int ntAll = np * 2 + (q >> 1);
        int k0 = 16 * kf + 2 * tg + 8 * r;
        int n  = 8 * ntAll + g;
        const float* Wm = mat ? Wc2 : W2;
        lo = Wm[k0 * HD + n];
        hi = Wm[(k0 + 1) * HD + n];
    } else {
        // head image: N=16 (n = e*AD + a for n<15), K=64 over hidden dim
        int t  = idx - (G1H + 4096);
        int kf = t >> 7;                     // 0..3
        int ntAll = (q >> 1);                // 0..1
        int k0 = 16 * kf + 2 * tg + 8 * r;
        int n  = 8 * ntAll + g;
        if (n < ED * AD) {
            int e = n / AD, a = n % AD;
            lo = Wh[e * HD * AD + k0 * AD + a];
            hi = Wh[e * HD * AD + (k0 + 1) * AD + a];
        }
    }
    half2 h = __floats2half2_rn(lo, hi);
    g_b[idx] = *reinterpret_cast<uint32_t*>(&h);
}

// ---------- main: persistent CTAs, 128 threads, 64 samples/tile, 4 CTAs/SM ----------
__global__ void __launch_bounds__(BLOCK, 4)
agent_mma(const float* __restrict__ x,   const int* __restrict__ action,
          const float* __restrict__ b1,  const float* __restrict__ b2,
          const float* __restrict__ bh,
          const float* __restrict__ bc1, const float* __restrict__ bc2,
          const float* __restrict__ Wc3, const float* __restrict__ bc3,
          float* __restrict__ out, int Bn, int ntiles)
{
    __shared__ __align__(16) float spool[4224];   // [0..2047] A bufs; [2048..4223] lbuf halves
    __shared__ float bhs[16];
    __shared__ float b1s[HD], b2s[HD], bc1s[HD], bc2s[HD], wc3s[HD];
    __shared__ float valbuf[2][ROWS];

    uint32_t* sp32 = (uint32_t*)spool;
    const uint4* gb4 = (const uint4*)g_b;
    const int   G2   = G1H / 4;
    const int   HB4  = (G1H + 4096) / 4;          // head image, uint4 units
    const uint32_t sbase = smem_u32(spool);

    const int tid   = threadIdx.x;
    const int lane  = tid & 31;
    const int warp  = tid >> 5;
    const int warpM = warp & 1;
    const int warpN = warp >> 1;
    const int g     = lane >> 2;
    const int tg    = lane & 3;
    const int rb2   = warpM * 32;

    // x staging geometry (R9-identical)
    const int kpair = tid & 15;
    const int rowb  = tid >> 4;
    const int kg_st = kpair >> 2;
    const int kw_st = kpair & 3;
    const int perm_st = ((rowb + 2 * kg_st) & 7);
    const int woff_st = kg_st * 32 + perm_st * 4 + kw_st;

    if (tid < ED * AD) bhs[tid] = bh[tid];
    if (tid < HD) {
        b1s[tid] = b1[tid];   b2s[tid] = b2[tid];
        bc1s[tid] = bc1[tid]; bc2s[tid] = bc2[tid]; wc3s[tid] = Wc3[tid];
    }
    const float bc3v = __ldg(&bc3[0]);
    __syncthreads();

    for (int tile = blockIdx.x; tile < ntiles; tile += gridDim.x) {
        const int s0 = tile * ROWS;

        float acc[2][8][4];
        #pragma unroll
        for (int t = 0; t < 2; t++)
            #pragma unroll
            for (int nt = 0; nt < 8; nt++)
                #pragma unroll
                for (int i = 0; i < 4; i++) acc[t][nt][i] = 0.f;

        // stage chunk 0 into A-buf0 (overlaps previous tile's head)
        #pragma unroll
        for (int it = 0; it < 8; it++) {
            int row = rowb + 8 * it;
            int srow = s0 + row; if (srow >= Bn) srow = Bn - 1;
            float2 v = __ldg((const float2*)(x + (size_t)srow * OBSD + 2 * kpair));
            sp32[it * 128 + woff_st] = pack_h2(v.x, v.y);
        }

        // ================= GEMM1: C[64x128] = X @ [W1|Wc1], 7 chunks =================
        #pragma unroll 1
        for (int c = 0; c < NCH1; c++) {
            float2 xq[8];
            if (c < NCH1 - 1) {
                int col0 = 32 * (c + 1) + 2 * kpair;
                #pragma unroll
                for (int it = 0; it < 8; it++) {
                    int row = rowb + 8 * it;
                    int srow = s0 + row; if (srow >= Bn) srow = Bn - 1;
                    xq[it] = (col0 < OBSD)
                        ? __ldg((const float2*)(x + (size_t)srow * OBSD + col0))
                        : make_float2(0.f, 0.f);
                }
            }
            __syncthreads();

            const uint32_t abuf = sbase + (c & 1) * 4096;
            const uint4* gbc = gb4 + c * 512 + warpN * 128 + lane;

            #pragma unroll
            for (int f = 0; f < 2; f++) {
                uint32_t A[2][4];
                #pragma unroll
                for (int t = 0; t < 2; t++) {
                    int mi = lane >> 3;
                    int rg = 4 * warpM + 2 * t + (mi & 1);
                    int kg = 2 * f + (mi >> 1);
                    int rowp = ((lane & 7) + 2 * kg) & 7;
                    ldsm4(A[t], abuf + (rg * 4 + kg) * 128 + rowp * 16);
                }
                #pragma unroll
                for (int npi = 0; npi < 4; npi++) {
                    uint4 bq = __ldg(gbc + f * 256 + npi * 32);
                    mma16(acc[0][2*npi],   A[0][0], A[0][1], A[0][2], A[0][3], bq.x, bq.y);
                    mma16(acc[1][2*npi],   A[1][0], A[1][1], A[1][2], A[1][3], bq.x, bq.y);
                    mma16(acc[0][2*npi+1], A[0][0], A[0][1], A[0][2], A[0][3], bq.z, bq.w);
                    mma16(acc[1][2*npi+1], A[1][0], A[1][1], A[1][2], A[1][3], bq.z, bq.w);
                }
            }

            if (c < NCH1 - 1) {
                uint32_t* bn = sp32 + ((c + 1) & 1) * 1024;
                #pragma unroll
                for (int it = 0; it < 8; it++)
                    bn[it * 128 + woff_st] = pack_h2(xq[it].x, xq[it].y);
            }
        }

        // epilogue1: bias + tanh (warpN0 = actor H, warpN1 = critic H)
        {
            const float* bA = warpN ? bc1s : b1s;
            #pragma unroll
            for (int t = 0; t < 2; t++)
                #pragma unroll
                for (int nt = 0; nt < 8; nt++) {
                    int n0 = 8 * nt + 2 * tg;
                    acc[t][nt][0] = tanha(acc[t][nt][0] + bA[n0]);
                    acc[t][nt][1] = tanha(acc[t][nt][1] + bA[n0 + 1]);
                    acc[t][nt][2] = tanha(acc[t][nt][2] + bA[n0]);
                    acc[t][nt][3] = tanha(acc[t][nt][3] + bA[n0 + 1]);
                }
        }

        // ================= GEMM2: critic pass (mat=1) then actor pass (mat=0) =================
        #pragma unroll 1
        for (int pp = 0; pp < 2; pp++) {
            const int mat = (pp == 0) ? 1 : 0;
            float acc2[2][4][4];
            #pragma unroll
            for (int t = 0; t < 2; t++)
                #pragma unroll
                for (int nt = 0; nt < 4; nt++)
                    #pragma unroll
                    for (int i = 0; i < 4; i++) acc2[t][nt][i] = 0.f;

            __syncthreads();
            if (warpN == mat) {                 // owner warps stage H (both kh buffers)
                #pragma unroll
                for (int t = 0; t < 2; t++)
                    #pragma unroll
                    for (int nt = 0; nt < 8; nt++) {
                        int kh = nt >> 2, kg = nt & 3;
                        uint32_t* buf = sp32 + kh * 1024;
                        int perm = (g + 2 * kg) & 7;
                        int rga = 4 * warpM + 2 * t;
                        buf[(rga * 4 + kg) * 32 + perm * 4 + tg] =
                            pack_h2(acc[t][nt][0], acc[t][nt][1]);
                        buf[((rga + 1) * 4 + kg) * 32 + perm * 4 + tg] =
                            pack_h2(acc[t][nt][2], acc[t][nt][3]);
                    }
            }
            __syncthreads();

            #pragma unroll
            for (int kh = 0; kh < 2; kh++) {
                const uint32_t abuf = sbase + kh * 4096;
                #pragma unroll
                for (int f = 0; f < 2; f++) {
                    uint32_t A[2][4];
                    #pragma unroll
                    for (int t = 0; t < 2; t++) {
                        int mi = lane >> 3;
                        int rg = 4 * warpM + 2 * t + (mi & 1);
                        int kg = 2 * f + (mi >> 1);
                        int rowp = ((lane & 7) + 2 * kg) & 7;
                        ldsm4(A[t], abuf + (rg * 4 + kg) * 128 + rowp * 16);
                    }
                    int kf = kh * 2 + f;
                    #pragma unroll
                    for (int npi = 0; npi < 2; npi++) {
                        uint4 bq = __ldg(&gb4[G2 + mat * 512 + kf * 128
                                              + warpN * 64 + npi * 32 + lane]);
                        mma16(acc2[0][2*npi],   A[0][0], A[0][1], A[0][2], A[0][3], bq.x, bq.y);
                        mma16(acc2[1][2*npi],   A[1][0], A[1][1], A[1][2], A[1][3], bq.x, bq.y);
                        mma16(acc2[0][2*npi+1], A[0][0], A[0][1], A[0][2], A[0][3], bq.z, bq.w);
                        mma16(acc2[1][2*npi+1], A[1][0], A[1][1], A[1][2], A[1][3], bq.z, bq.w);
                    }
                }
            }

            if (mat == 1) {
                float vr[4] = {0.f, 0.f, 0.f, 0.f};
                #pragma unroll
                for (int t = 0; t < 2; t++)
                    #pragma unroll
                    for (int nt = 0; nt < 4; nt++) {
                        int n0 = warpN * 32 + 8 * nt + 2 * tg;
                        vr[2*t]   = fmaf(tanha(acc2[t][nt][0] + bc2s[n0]),     wc3s[n0],     vr[2*t]);
                        vr[2*t]   = fmaf(tanha(acc2[t][nt][1] + bc2s[n0 + 1]), wc3s[n0 + 1], vr[2*t]);
                        vr[2*t+1] = fmaf(tanha(acc2[t][nt][2] + bc2s[n0]),     wc3s[n0],     vr[2*t+1]);
                        vr[2*t+1] = fmaf(tanha(acc2[t][nt][3] + bc2s[n0 + 1]), wc3s[n0 + 1], vr[2*t+1]);
                    }
                #pragma unroll
                for (int i = 0; i < 4; i++) {
                    vr[i] += __shfl_xor_sync(0xFFFFFFFF, vr[i], 1);
                    vr[i] += __shfl_xor_sync(0xFFFFFFFF, vr[i], 2);
                }
                if (tg == 0) {
                    valbuf[warpN][rb2 + g]      = vr[0];
                    valbuf[warpN][rb2 + g + 8]  = vr[1];
                    valbuf[warpN][rb2 + g + 16] = vr[2];
                    valbuf[warpN][rb2 + g + 24] = vr[3];
                }
            } else {
                // actor: tanh -> feat fragments, then head GEMM (N=16: all 3 event heads)
                #pragma unroll
                for (int t = 0; t < 2; t++)
                    #pragma unroll
                    for (int nt = 0; nt < 4; nt++) {
                        int n0 = warpN * 32 + 8 * nt + 2 * tg;
                        acc2[t][nt][0] = tanha(acc2[t][nt][0] + b2s[n0]);
                        acc2[t][nt][1] = tanha(acc2[t][nt][1] + b2s[n0 + 1]);
                        acc2[t][nt][2] = tanha(acc2[t][nt][2] + b2s[n0]);
                        acc2[t][nt][3] = tanha(acc2[t][nt][3] + b2s[n0 + 1]);
                    }
                float acc3[2][2][4];
                #pragma unroll
                for (int t = 0; t < 2; t++)
                    #pragma unroll
                    for (int nb = 0; nb < 2; nb++)
                        #pragma unroll
                        for (int i = 0; i < 4; i++) acc3[t][nb][i] = 0.f;

                #pragma unroll
                for (int t = 0; t < 2; t++)
                    #pragma unroll
                    for (int kfl = 0; kfl < 2; kfl++) {
                        // feat fragments ARE A fragments over the hidden dim
                        uint32_t A0 = pack_h2(acc2[t][2*kfl][0],   acc2[t][2*kfl][1]);
                        uint32_t A1 = pack_h2(acc2[t][2*kfl][2],   acc2[t][2*kfl][3]);
                        uint32_t A2 = pack_h2(acc2[t][2*kfl+1][0], acc2[t][2*kfl+1][1]);
                        uint32_t A3 = pack_h2(acc2[t][2*kfl+1][2], acc2[t][2*kfl+1][3]);
                        int kf = 2 * warpN + kfl;
                        uint4 bq = __ldg(&gb4[HB4 + kf * 32 + lane]);
                        mma16(acc3[t][0], A0, A1, A2, A3, bq.x, bq.y);
                        mma16(acc3[t][1], A0, A1, A2, A3, bq.z, bq.w);
                    }
                // store k-half partial logits
                float* lb = spool + 2048 + warpN * 1088;   // 64 x 17
                #pragma unroll
                for (int t = 0; t < 2; t++)
                    #pragma unroll
                    for (int nb = 0; nb < 2; nb++) {
                        int n0 = 8 * nb + 2 * tg;
                        int r0 = (rb2 + 16 * t + g) * 17;
                        int r1 = r0 + 8 * 17;
                        lb[r0 + n0]     = acc3[t][nb][0];
                        lb[r0 + n0 + 1] = acc3[t][nb][1];
                        lb[r1 + n0]     = acc3[t][nb][2];
                        lb[r1 + n0 + 1] = acc3[t][nb][3];
                    }
                __syncthreads();
            }
        }

        // ================= per-sample head (now trivial) =================
        if (tid < ROWS) {
            int s = s0 + tid;
            int sr = (s < Bn) ? s : (Bn - 1);
            const float* xrow = x + (size_t)sr * OBSD;
            float x0 = __ldg(&xrow[0]), x1v = __ldg(&xrow[1]), x2v = __ldg(&xrow[2]);
            int ev = 0; float bx = x0;
            if (x1v > bx) { bx = x1v; ev = 1; }
            if (x2v > bx) { ev = 2; }

            const float* lb0 = spool + 2048;
            const float* lb1 = spool + 2048 + 1088;
            int base = tid * 17 + ev * AD;
            float lg[AD];
            #pragma unroll
            for (int a = 0; a < AD; a++)
                lg[a] = lb0[base + a] + lb1[base + a] + bhs[ev * AD + a];

            float m = lg[0];
            #pragma unroll
            for (int a = 1; a < AD; a++) m = fmaxf(m, lg[a]);
            float se = 0.f;
            #pragma unroll
            for (int a = 0; a < AD; a++) se += __expf(lg[a] - m);
            float lse = __logf(se);
            float ent = 0.f;
            #pragma unroll
            for (int a = 0; a < AD; a++) {
                float lp = lg[a] - m - lse;
                ent -= __expf(lp) * lp;
            }
            int   act  = __ldg(&action[sr]);
            float logp = lg[act] - m - lse;

            if (s < Bn) {
                out[s]          = (float)act;
                out[Bn + s]     = logp;
                out[2 * Bn + s] = ent;
                out[3 * Bn + s] = valbuf[0][tid] + valbuf[1][tid] + bc3v;
            }
        }
    }
}

extern "C" void kernel_launch(void* const* d_in, const int* in_sizes, int n_in,
                              void* d_out, int out_size) {
    const float* x    = (const float*)d_in[0];
    const int*   act  = (const int*)  d_in[1];
    const float* W1   = (const float*)d_in[2];
    const float* b1   = (const float*)d_in[3];
    const float* W2   = (const float*)d_in[4];
    const float* b2   = (const float*)d_in[5];
    const float* Wh   = (const float*)d_in[6];
    const float* bh   = (const float*)d_in[7];
    const float* Wc1  = (const float*)d_in[8];
    const float* bc1  = (const float*)d_in[9];
    const float* Wc2  = (const float*)d_in[10];
    const float* bc2  = (const float*)d_in[11];
    const float* Wc3  = (const float*)d_in[12];
    const float* bc3  = (const float*)d_in[13];
    float* out = (float*)d_out;

    const int Bn = in_sizes[1];

    prep_b<<<(GTOT32 + 255) / 256, 256>>>(W1, Wc1, W2, Wc2, Wh);

    const int ntiles = (Bn + ROWS - 1) / ROWS;
    const int grid   = (ntiles < 608) ? ntiles : 608;   // 4 CTAs x 152 SMs
    agent_mma<<<grid, BLOCK>>>(x, act, b1, b2, bh, bc1, bc2, Wc3, bc3, out, Bn, ntiles);
}